// round 14
// baseline (speedup 1.0000x reference)
#include <cuda_runtime.h>
#include <cuda_fp16.h>
#include <math.h>
#include <stdint.h>

// Problem constants
#define BB   4
#define TT   2048
#define CC   1024
#define NH   16
#define DD   64
#define MROWS (BB*TT)                      // 8192
#define OUT_ELEMS ((size_t)BB*TT*CC)       // 8388608

// Scratch (device globals — no allocation allowed). All intermediates fp16.
__device__ __half g_x[(size_t)MROWS*CC];           // f16 x
__device__ __half g_wt[4*(size_t)CC*CC];           // W^T f16 (q,k,v,o)
__device__ __half g_q[(size_t)BB*NH*TT*DD];        // [bn][t][d]
__device__ __half g_k[(size_t)BB*NH*TT*DD];        // [bn][t][d]
__device__ __half g_v[(size_t)BB*NH*TT*DD];        // [bn][d][t]  (transposed)
__device__ __half g_attn[(size_t)MROWS*CC];        // [b][t][n*64+d]
__device__ __half g_pw[(size_t)BB*NH*TT*TT];       // unnormalized exp weights (f16)
__device__ float  g_linv[(size_t)BB*NH*TT];        // 1/rowsum

// ---------------------------------------------------------------------------
// PTX helpers
// ---------------------------------------------------------------------------
__device__ __forceinline__ uint32_t smem_u32(const void* p) {
    return (uint32_t)__cvta_generic_to_shared(p);
}
__device__ __forceinline__ void ldsm4(uint32_t a, uint32_t& r0, uint32_t& r1,
                                      uint32_t& r2, uint32_t& r3) {
    asm volatile("ldmatrix.sync.aligned.m8n8.x4.shared.b16 {%0,%1,%2,%3}, [%4];"
                 : "=r"(r0), "=r"(r1), "=r"(r2), "=r"(r3) : "r"(a));
}
// f16 mma: D(f32) += A(f16,4reg) @ B(f16,2reg), m16n8k16
__device__ __forceinline__ void mma_f16(float& c0, float& c1, float& c2, float& c3,
                                        uint32_t a0, uint32_t a1, uint32_t a2, uint32_t a3,
                                        uint32_t b0, uint32_t b1) {
    asm volatile(
        "mma.sync.aligned.m16n8k16.row.col.f32.f16.f16.f32 "
        "{%0,%1,%2,%3}, {%4,%5,%6,%7}, {%8,%9}, {%0,%1,%2,%3};"
        : "+f"(c0), "+f"(c1), "+f"(c2), "+f"(c3)
        : "r"(a0), "r"(a1), "r"(a2), "r"(a3), "r"(b0), "r"(b1));
}
__device__ __forceinline__ void cpasync16(uint32_t saddr, const void* g) {
    asm volatile("cp.async.cg.shared.global [%0], [%1], 16;" :: "r"(saddr), "l"(g));
}
#define CP_COMMIT asm volatile("cp.async.commit_group;")
#define CP_WAIT1  asm volatile("cp.async.wait_group 1;")
#define CP_WAIT0  asm volatile("cp.async.wait_group 0;")

// ---------------------------------------------------------------------------
// Pre-pass: convert x to f16 (8 elems/thread)
// ---------------------------------------------------------------------------
__global__ __launch_bounds__(256) void round_x_kernel(const float* __restrict__ x)
{
    size_t i = ((size_t)blockIdx.x * 256 + threadIdx.x) * 8;
    float4 a = *(const float4*)(x + i);
    float4 b = *(const float4*)(x + i + 4);
    __half2 h[4];
    h[0] = __floats2half2_rn(a.x, a.y);
    h[1] = __floats2half2_rn(a.z, a.w);
    h[2] = __floats2half2_rn(b.x, b.y);
    h[3] = __floats2half2_rn(b.z, b.w);
    *(uint4*)(g_x + i) = *(uint4*)h;
}

// Pre-pass: transpose + convert ALL FOUR weight matrices (blockIdx.z selects)
__global__ __launch_bounds__(256) void transpose_w_all(const float* __restrict__ W0,
                                                       const float* __restrict__ W1,
                                                       const float* __restrict__ W2,
                                                       const float* __restrict__ W3)
{
    __shared__ float tile[32][33];
    const int which = blockIdx.z;
    const float* __restrict__ W = (which == 0) ? W0 : (which == 1) ? W1
                                : (which == 2) ? W2 : W3;
    int bx = blockIdx.x * 32, by = blockIdx.y * 32;
    int tx = threadIdx.x & 31, ty = threadIdx.x >> 5;   // 32 x 8
    #pragma unroll
    for (int i = 0; i < 4; i++)
        tile[ty + 8 * i][tx] = W[(size_t)(by + ty + 8 * i) * CC + bx + tx];
    __syncthreads();
    __half* dst = g_wt + (size_t)which * CC * CC;
    #pragma unroll
    for (int i = 0; i < 4; i++)
        dst[(size_t)(bx + ty + 8 * i) * CC + by + tx] =
            __float2half_rn(tile[tx][ty + 8 * i]);
}

// ---------------------------------------------------------------------------
// f16 GEMM body: C(128x128 tile) = A @ W, 3-stage cp.async pipeline.
// CTA 256 thr, warp tile 64x32, BK=32.  smem pitch 40 halfs (80B).
// mode 0/1: Q/K -> [bn][t][d].  mode 2: V -> [bn][d][t].  mode 3: fp32 out.
// ---------------------------------------------------------------------------
#define GPH 40
#define GSTAGE_B (128 * GPH * 2)          // 10240 bytes per operand stage
#define GEMM_SMEM (6 * GSTAGE_B)          // 3 stages x (A + B)

__device__ __forceinline__ void gemm_body(
    const __half* __restrict__ A, const __half* __restrict__ BT,
    const float* __restrict__ bias, float* __restrict__ dst_ext,
    int mode, char* smem, int bm, int bnc)
{
    const uint32_t sA = smem_u32(smem);                  // [3][GSTAGE_B]
    const uint32_t sB = sA + 3 * GSTAGE_B;               // [3][GSTAGE_B]

    const int t = threadIdx.x, lane = t & 31, warp = t >> 5;
    const int wm = (warp >> 2) * 64, wn = (warp & 3) * 32;

    float acc[4][4][4] = {};

    auto load_stage = [&](int ks, int buf) {
        int k0 = ks * 32;
        int row = t >> 1;                 // 0..127
        int half0 = (t & 1) << 4;         // 0 or 16 halfs
        uint32_t so = (uint32_t)(buf * GSTAGE_B + row * (GPH * 2) + half0 * 2);
        cpasync16(sA + so,      A  + (size_t)(bm + row) * CC + k0 + half0);
        cpasync16(sA + so + 16, A  + (size_t)(bm + row) * CC + k0 + half0 + 8);
        cpasync16(sB + so,      BT + (size_t)(bnc + row) * CC + k0 + half0);
        cpasync16(sB + so + 16, BT + (size_t)(bnc + row) * CC + k0 + half0 + 8);
        CP_COMMIT;
    };

    load_stage(0, 0);
    load_stage(1, 1);

    int buf = 0;
    int nbuf = 2;                          // buffer for the next issued load
    for (int ks = 0; ks < 32; ks++) {
        if (ks < 31) { CP_WAIT1; } else { CP_WAIT0; }
        __syncthreads();
        if (ks + 2 < 32) {
            load_stage(ks + 2, nbuf);
            if (++nbuf == 3) nbuf = 0;
        }

        #pragma unroll
        for (int kk = 0; kk < 2; kk++) {            // two k16 steps per BK=32
            uint32_t af[4][4];
            #pragma unroll
            for (int mt = 0; mt < 4; mt++) {
                uint32_t a = sA + (uint32_t)(buf * GSTAGE_B +
                              (wm + mt * 16 + (lane & 15)) * (GPH * 2) +
                              (kk * 16 + ((lane >> 4) << 3)) * 2);
                ldsm4(a, af[mt][0], af[mt][1], af[mt][2], af[mt][3]);
            }
            #pragma unroll
            for (int ntp = 0; ntp < 2; ntp++) {
                uint32_t b0, b1, b2, b3;
                uint32_t a = sB + (uint32_t)(buf * GSTAGE_B +
                              (wn + ntp * 16 + (lane & 7) + ((lane >> 4) << 3)) * (GPH * 2) +
                              (kk * 16 + (((lane >> 3) & 1) << 3)) * 2);
                ldsm4(a, b0, b1, b2, b3);
                #pragma unroll
                for (int mt = 0; mt < 4; mt++) {
                    mma_f16(acc[mt][2*ntp][0],   acc[mt][2*ntp][1],
                            acc[mt][2*ntp][2],   acc[mt][2*ntp][3],
                            af[mt][0], af[mt][1], af[mt][2], af[mt][3], b0, b1);
                    mma_f16(acc[mt][2*ntp+1][0], acc[mt][2*ntp+1][1],
                            acc[mt][2*ntp+1][2], acc[mt][2*ntp+1][3],
                            af[mt][0], af[mt][1], af[mt][2], af[mt][3], b2, b3);
                }
            }
        }
        __syncthreads();
        if (++buf == 3) buf = 0;
    }

    // Epilogue
    #pragma unroll
    for (int mt = 0; mt < 4; mt++) {
        #pragma unroll
        for (int nt = 0; nt < 4; nt++) {
            int r = bm + wm + mt * 16 + (lane >> 2);
            int c = bnc + wn + nt * 8 + ((lane & 3) << 1);
            float bv0 = bias[c], bv1 = bias[c + 1];
            float v0 = acc[mt][nt][0] + bv0, v1 = acc[mt][nt][1] + bv1;
            float v2 = acc[mt][nt][2] + bv0, v3 = acc[mt][nt][3] + bv1;
            if (mode == 3) {
                *(float2*)(dst_ext + (size_t)r * CC + c)       = make_float2(v0, v1);
                *(float2*)(dst_ext + (size_t)(r + 8) * CC + c) = make_float2(v2, v3);
            } else {
                int b = r >> 11, tt = r & 2047;
                int hn = c >> 6, d = c & 63;
                size_t bnix = (size_t)(b * NH + hn);
                if (mode == 2) {
                    g_v[(bnix * DD + d)     * TT + tt]     = __float2half_rn(v0);
                    g_v[(bnix * DD + d + 1) * TT + tt]     = __float2half_rn(v1);
                    g_v[(bnix * DD + d)     * TT + tt + 8] = __float2half_rn(v2);
                    g_v[(bnix * DD + d + 1) * TT + tt + 8] = __float2half_rn(v3);
                } else {
                    __half* dst = (mode == 0) ? g_q : g_k;
                    *(__half2*)(dst + (bnix * TT + tt) * DD + d) =
                        __floats2half2_rn(v0, v1);
                    *(__half2*)(dst + (bnix * TT + tt + 8) * DD + d) =
                        __floats2half2_rn(v2, v3);
                }
            }
        }
    }
}

// Fused QKV projection: grid (64, 8, 3); blockIdx.z = mode/W select
__global__ __launch_bounds__(256) void gemm_qkv(const float* __restrict__ bq,
                                                const float* __restrict__ bk,
                                                const float* __restrict__ bv)
{
    extern __shared__ char smem[];
    const int z = blockIdx.z;
    const float* bias = (z == 0) ? bq : (z == 1) ? bk : bv;
    gemm_body(g_x, g_wt + (size_t)z * CC * CC, bias, nullptr, z, smem,
              blockIdx.x * 128, blockIdx.y * 128);
}

// Output projection
__global__ __launch_bounds__(256) void gemm_out(const float* __restrict__ bo,
                                                float* __restrict__ out)
{
    extern __shared__ char smem[];
    gemm_body(g_attn, g_wt + 3 * (size_t)CC * CC, bo, out, 3, smem,
              blockIdx.x * 128, blockIdx.y * 128);
}

// ---------------------------------------------------------------------------
// Single-pass causal attention (f16 mma).  P fragments for the PV mma are
// formed IN REGISTERS from the score accumulators (A-frag of m16n8k16 ==
// C-frag layout of the QK^T mma) — no smem staging, no P ldmatrix.
// Writes UNNORMALIZED exp weights (f16, direct half2 stores) to g_pw,
// 1/rowsum to g_linv, normalized O (f16) to g_attn.
// Grid (32 qtiles reversed, 64 bn), block 128 (4 warps x 16 q-rows).
// smem pitch 72 halfs (144B) -> conflict-free b16 ldmatrix.
// ---------------------------------------------------------------------------
#define APH 72
#define ATTN_SMEM (3 * 64 * APH * 2)

__global__ __launch_bounds__(128) void attn_f16(void)
{
    extern __shared__ char smc[];
    __half* Qs = (__half*)smc;            // [64][APH]
    __half* Ks = Qs + 64 * APH;           // [64][APH]  [tok][d]
    __half* Vs = Ks + 64 * APH;           // [64][APH]  [d][tok]

    const int t = threadIdx.x, lane = t & 31, wid = t >> 5;
    const int qb = gridDim.x - 1 - blockIdx.x;   // longest blocks first
    const int bn = blockIdx.y;
    const int q0 = qb * 64;

    const __half* __restrict__ Qg = g_q + (size_t)bn * TT * DD;
    const __half* __restrict__ Kg = g_k + (size_t)bn * TT * DD;
    const __half* __restrict__ Vg = g_v + (size_t)bn * DD * TT;

    // Load Q tile [64][64] halfs
    #pragma unroll
    for (int i = 0; i < 4; i++) {
        int lin = t + 128 * i;            // 0..511
        int row = lin >> 3;               // 0..63
        int c8  = (lin & 7) << 3;         // 0..56
        *(uint4*)(Qs + row * APH + c8) = *(const uint4*)(Qg + (size_t)(q0 + row) * DD + c8);
    }
    __syncthreads();

    const uint32_t sQ = smem_u32(Qs), sK = smem_u32(Ks), sV = smem_u32(Vs);

    // Q fragments (persistent): 4 k16-steps x 4 regs
    uint32_t qf[4][4];
    #pragma unroll
    for (int ds = 0; ds < 4; ds++) {
        uint32_t a = sQ + (uint32_t)(((wid * 16 + (lane & 15)) * APH +
                          ds * 16 + ((lane >> 4) << 3)) << 1);
        ldsm4(a, qf[ds][0], qf[ds][1], qf[ds][2], qf[ds][3]);
    }

    float o[8][4] = {};
    float l0 = 0.f, l1 = 0.f;
    const int rl = lane >> 2;
    const int cl = (lane & 3) << 1;
    const int rowg0 = q0 + wid * 16 + rl;
    const int rowg1 = rowg0 + 8;
    __half* prow0 = g_pw + ((size_t)bn * TT + rowg0) * TT;
    __half* prow1 = g_pw + ((size_t)bn * TT + rowg1) * TT;

    for (int kt = 0; kt <= qb; kt++) {
        __syncthreads();
        #pragma unroll
        for (int i = 0; i < 4; i++) {
            int lin = t + 128 * i;
            int row = lin >> 3;
            int c8  = (lin & 7) << 3;
            *(uint4*)(Ks + row * APH + c8) =
                *(const uint4*)(Kg + (size_t)(kt * 64 + row) * DD + c8);
            *(uint4*)(Vs + row * APH + c8) =
                *(const uint4*)(Vg + (size_t)row * TT + kt * 64 + c8);
        }
        __syncthreads();

        // ---- scores + exp; P halves kept in registers ----
        uint32_t ph[8][2];                 // [nt] {h01(rows rl), h23(rows rl+8)}
        #pragma unroll
        for (int ntp = 0; ntp < 4; ntp++) {
            float sa[2][4] = {};
            #pragma unroll
            for (int ds = 0; ds < 4; ds++) {
                uint32_t b0, b1, b2, b3;
                uint32_t a = sK + (uint32_t)(((ntp * 16 + (lane & 7) + ((lane >> 4) << 3)) * APH +
                                  ds * 16 + (((lane >> 3) & 1) << 3)) << 1);
                ldsm4(a, b0, b1, b2, b3);
                mma_f16(sa[0][0], sa[0][1], sa[0][2], sa[0][3],
                        qf[ds][0], qf[ds][1], qf[ds][2], qf[ds][3], b0, b1);
                mma_f16(sa[1][0], sa[1][1], sa[1][2], sa[1][3],
                        qf[ds][0], qf[ds][1], qf[ds][2], qf[ds][3], b2, b3);
            }
            #pragma unroll
            for (int h = 0; h < 2; h++) {
                int nt = 2 * ntp + h;
                int colg = kt * 64 + nt * 8 + cl;
                float p0 = __expf(sa[h][0] * 0.125f);
                float p1 = __expf(sa[h][1] * 0.125f);
                float p2 = __expf(sa[h][2] * 0.125f);
                float p3 = __expf(sa[h][3] * 0.125f);
                if (kt == qb) {
                    if (colg     > rowg0) p0 = 0.f;
                    if (colg + 1 > rowg0) p1 = 0.f;
                    if (colg     > rowg1) p2 = 0.f;
                    if (colg + 1 > rowg1) p3 = 0.f;
                }
                __half2 h01 = __floats2half2_rn(p0, p1);
                __half2 h23 = __floats2half2_rn(p2, p3);
                float2 f01 = __half22float2(h01);
                float2 f23 = __half22float2(h23);
                l0 += f01.x + f01.y;
                l1 += f23.x + f23.y;
                *(__half2*)(prow0 + colg) = h01;
                *(__half2*)(prow1 + colg) = h23;
                ph[nt][0] = *(uint32_t*)&h01;
                ph[nt][1] = *(uint32_t*)&h23;
            }
        }

        // ---- O += P @ V  (P A-frags straight from ph) ----
        #pragma unroll
        for (int ntp = 0; ntp < 4; ntp++) {
            #pragma unroll
            for (int kp = 0; kp < 4; kp++) {
                uint32_t b0, b1, b2, b3;
                uint32_t a = sV + (uint32_t)(((ntp * 16 + (lane & 7) + ((lane >> 4) << 3)) * APH +
                                  kp * 16 + (((lane >> 3) & 1) << 3)) << 1);
                ldsm4(a, b0, b1, b2, b3);
                mma_f16(o[2*ntp][0], o[2*ntp][1], o[2*ntp][2], o[2*ntp][3],
                        ph[2*kp][0], ph[2*kp][1], ph[2*kp+1][0], ph[2*kp+1][1], b0, b1);
                mma_f16(o[2*ntp+1][0], o[2*ntp+1][1], o[2*ntp+1][2], o[2*ntp+1][3],
                        ph[2*kp][0], ph[2*kp][1], ph[2*kp+1][0], ph[2*kp+1][1], b2, b3);
            }
        }
    }

    // row sums -> 1/l
    l0 += __shfl_xor_sync(0xffffffffu, l0, 1);
    l0 += __shfl_xor_sync(0xffffffffu, l0, 2);
    l1 += __shfl_xor_sync(0xffffffffu, l1, 1);
    l1 += __shfl_xor_sync(0xffffffffu, l1, 2);
    float li0 = 1.f / l0, li1 = 1.f / l1;

    // store O (normalized, f16) in [b][t][hn*64+d]
    int b = bn >> 4, hn = bn & 15;
    __half* Og0 = g_attn + ((size_t)b * TT + rowg0) * CC + hn * DD;
    __half* Og1 = g_attn + ((size_t)b * TT + rowg1) * CC + hn * DD;
    #pragma unroll
    for (int nt = 0; nt < 8; nt++) {
        *(__half2*)(Og0 + nt * 8 + cl) = __floats2half2_rn(o[nt][0] * li0, o[nt][1] * li0);
        *(__half2*)(Og1 + nt * 8 + cl) = __floats2half2_rn(o[nt][2] * li1, o[nt][3] * li1);
    }
    if ((lane & 3) == 0) {
        g_linv[(size_t)bn * TT + rowg0] = li0;
        g_linv[(size_t)bn * TT + rowg1] = li1;
    }
}

// ---------------------------------------------------------------------------
// Produce final fp32 weights: normalize f16 staging for cols<=q, zeros above.
// One block (256 threads) per row; writes the FULL 2048-col row once.
// ---------------------------------------------------------------------------
__global__ __launch_bounds__(256) void scale_w_kernel(float* __restrict__ w)
{
    int R = blockIdx.x;                  // 0 .. 64*2048-1
    int q = R & 2047;
    float li = g_linv[R];
    const __half* src = g_pw + (size_t)R * TT;
    float* row = w + (size_t)R * TT;
    #pragma unroll
    for (int i = 0; i < 2; i++) {
        int col = (threadIdx.x + (i << 8)) << 2;
        float4 v;
        if (col <= q) {
            __half2 a = *(const __half2*)(src + col);
            __half2 b = *(const __half2*)(src + col + 2);
            float2 fa = __half22float2(a);
            float2 fb = __half22float2(b);
            v.x = fa.x * li;
            v.y = (col + 1 <= q) ? fa.y * li : 0.f;
            v.z = (col + 2 <= q) ? fb.x * li : 0.f;
            v.w = (col + 3 <= q) ? fb.y * li : 0.f;
        } else {
            v = make_float4(0.f, 0.f, 0.f, 0.f);
        }
        *(float4*)(row + col) = v;
    }
}

// ---------------------------------------------------------------------------
extern "C" void kernel_launch(void* const* d_in, const int* in_sizes, int n_in,
                              void* d_out, int out_size)
{
    const float* x  = (const float*)d_in[0];
    const float* Wq = (const float*)d_in[1];
    const float* bq = (const float*)d_in[2];
    const float* Wk = (const float*)d_in[3];
    const float* bk = (const float*)d_in[4];
    const float* Wv = (const float*)d_in[5];
    const float* bv = (const float*)d_in[6];
    const float* Wo = (const float*)d_in[7];
    const float* bo = (const float*)d_in[8];
    float* out = (float*)d_out;
    float* w_out = out + OUT_ELEMS;

    cudaFuncSetAttribute(gemm_qkv, cudaFuncAttributeMaxDynamicSharedMemorySize, GEMM_SMEM);
    cudaFuncSetAttribute(gemm_out, cudaFuncAttributeMaxDynamicSharedMemorySize, GEMM_SMEM);
    cudaFuncSetAttribute(attn_f16, cudaFuncAttributeMaxDynamicSharedMemorySize, ATTN_SMEM);

    // Pre-pass
    round_x_kernel<<<(MROWS * CC) / (256 * 8), 256>>>(x);
    dim3 tg(32, 32, 4);
    transpose_w_all<<<tg, 256>>>(Wq, Wk, Wv, Wo);

    dim3 gq(MROWS / 128, CC / 128, 3);
    gemm_qkv<<<gq, 256, GEMM_SMEM>>>(bq, bk, bv);

    dim3 ag(TT / 64, BB * NH);
    attn_f16<<<ag, 128, ATTN_SMEM>>>();

    dim3 gg(MROWS / 128, CC / 128);
    gemm_out<<<gg, 256, GEMM_SMEM>>>(bo, out);

    scale_w_kernel<<<BB * NH * TT, 256>>>(w_out);
}

// round 15
// speedup vs baseline: 1.0688x; 1.0688x over previous
#include <cuda_runtime.h>
#include <cuda_fp16.h>
#include <math.h>
#include <stdint.h>

// Problem constants
#define BB   4
#define TT   2048
#define CC   1024
#define NH   16
#define DD   64
#define MROWS (BB*TT)                      // 8192
#define OUT_ELEMS ((size_t)BB*TT*CC)       // 8388608

// Scratch (device globals — no allocation allowed). All intermediates fp16.
__device__ __half g_x[(size_t)MROWS*CC];           // f16 x
__device__ __half g_wt[4*(size_t)CC*CC];           // W^T f16 (q,k,v,o)
__device__ __half g_q[(size_t)BB*NH*TT*DD];        // [bn][t][d]
__device__ __half g_k[(size_t)BB*NH*TT*DD];        // [bn][t][d]
__device__ __half g_v[(size_t)BB*NH*TT*DD];        // [bn][d][t]  (transposed)
__device__ __half g_attn[(size_t)MROWS*CC];        // [b][t][n*64+d]
__device__ __half g_pw[(size_t)BB*NH*TT*TT];       // unnormalized exp weights (f16)
__device__ float  g_linv[(size_t)BB*NH*TT];        // 1/rowsum

// ---------------------------------------------------------------------------
// PTX helpers
// ---------------------------------------------------------------------------
__device__ __forceinline__ uint32_t smem_u32(const void* p) {
    return (uint32_t)__cvta_generic_to_shared(p);
}
__device__ __forceinline__ void ldsm4(uint32_t a, uint32_t& r0, uint32_t& r1,
                                      uint32_t& r2, uint32_t& r3) {
    asm volatile("ldmatrix.sync.aligned.m8n8.x4.shared.b16 {%0,%1,%2,%3}, [%4];"
                 : "=r"(r0), "=r"(r1), "=r"(r2), "=r"(r3) : "r"(a));
}
// f16 mma: D(f32) += A(f16,4reg) @ B(f16,2reg), m16n8k16
__device__ __forceinline__ void mma_f16(float& c0, float& c1, float& c2, float& c3,
                                        uint32_t a0, uint32_t a1, uint32_t a2, uint32_t a3,
                                        uint32_t b0, uint32_t b1) {
    asm volatile(
        "mma.sync.aligned.m16n8k16.row.col.f32.f16.f16.f32 "
        "{%0,%1,%2,%3}, {%4,%5,%6,%7}, {%8,%9}, {%0,%1,%2,%3};"
        : "+f"(c0), "+f"(c1), "+f"(c2), "+f"(c3)
        : "r"(a0), "r"(a1), "r"(a2), "r"(a3), "r"(b0), "r"(b1));
}
__device__ __forceinline__ void cpasync16(uint32_t saddr, const void* g) {
    asm volatile("cp.async.cg.shared.global [%0], [%1], 16;" :: "r"(saddr), "l"(g));
}
#define CP_COMMIT asm volatile("cp.async.commit_group;")
#define CP_WAIT1  asm volatile("cp.async.wait_group 1;")
#define CP_WAIT0  asm volatile("cp.async.wait_group 0;")

// ---------------------------------------------------------------------------
// Pre-pass: convert x to f16 (8 elems/thread)
// ---------------------------------------------------------------------------
__global__ __launch_bounds__(256) void round_x_kernel(const float* __restrict__ x)
{
    size_t i = ((size_t)blockIdx.x * 256 + threadIdx.x) * 8;
    float4 a = *(const float4*)(x + i);
    float4 b = *(const float4*)(x + i + 4);
    __half2 h[4];
    h[0] = __floats2half2_rn(a.x, a.y);
    h[1] = __floats2half2_rn(a.z, a.w);
    h[2] = __floats2half2_rn(b.x, b.y);
    h[3] = __floats2half2_rn(b.z, b.w);
    *(uint4*)(g_x + i) = *(uint4*)h;
}

// Pre-pass: transpose + convert ALL FOUR weight matrices (blockIdx.z selects)
__global__ __launch_bounds__(256) void transpose_w_all(const float* __restrict__ W0,
                                                       const float* __restrict__ W1,
                                                       const float* __restrict__ W2,
                                                       const float* __restrict__ W3)
{
    __shared__ float tile[32][33];
    const int which = blockIdx.z;
    const float* __restrict__ W = (which == 0) ? W0 : (which == 1) ? W1
                                : (which == 2) ? W2 : W3;
    int bx = blockIdx.x * 32, by = blockIdx.y * 32;
    int tx = threadIdx.x & 31, ty = threadIdx.x >> 5;   // 32 x 8
    #pragma unroll
    for (int i = 0; i < 4; i++)
        tile[ty + 8 * i][tx] = W[(size_t)(by + ty + 8 * i) * CC + bx + tx];
    __syncthreads();
    __half* dst = g_wt + (size_t)which * CC * CC;
    #pragma unroll
    for (int i = 0; i < 4; i++)
        dst[(size_t)(bx + ty + 8 * i) * CC + by + tx] =
            __float2half_rn(tile[tx][ty + 8 * i]);
}

// ---------------------------------------------------------------------------
// f16 GEMM body: C(128x128 tile) = A @ W, 3-stage cp.async pipeline.
// CTA 256 thr, warp tile 64x32, BK=32.  smem pitch 40 halfs (80B).
// mode 0/1: Q/K -> [bn][t][d].  mode 2: V -> [bn][d][t].  mode 3: fp32 out.
// ---------------------------------------------------------------------------
#define GPH 40
#define GSTAGE_B (128 * GPH * 2)          // 10240 bytes per operand stage
#define GEMM_SMEM (6 * GSTAGE_B)          // 3 stages x (A + B)

__device__ __forceinline__ void gemm_body(
    const __half* __restrict__ A, const __half* __restrict__ BT,
    const float* __restrict__ bias, float* __restrict__ dst_ext,
    int mode, char* smem, int bm, int bnc)
{
    const uint32_t sA = smem_u32(smem);                  // [3][GSTAGE_B]
    const uint32_t sB = sA + 3 * GSTAGE_B;               // [3][GSTAGE_B]

    const int t = threadIdx.x, lane = t & 31, warp = t >> 5;
    const int wm = (warp >> 2) * 64, wn = (warp & 3) * 32;

    float acc[4][4][4] = {};

    auto load_stage = [&](int ks, int buf) {
        int k0 = ks * 32;
        int row = t >> 1;                 // 0..127
        int half0 = (t & 1) << 4;         // 0 or 16 halfs
        uint32_t so = (uint32_t)(buf * GSTAGE_B + row * (GPH * 2) + half0 * 2);
        cpasync16(sA + so,      A  + (size_t)(bm + row) * CC + k0 + half0);
        cpasync16(sA + so + 16, A  + (size_t)(bm + row) * CC + k0 + half0 + 8);
        cpasync16(sB + so,      BT + (size_t)(bnc + row) * CC + k0 + half0);
        cpasync16(sB + so + 16, BT + (size_t)(bnc + row) * CC + k0 + half0 + 8);
        CP_COMMIT;
    };

    load_stage(0, 0);
    load_stage(1, 1);

    int buf = 0;
    int nbuf = 2;                          // buffer for the next issued load
    for (int ks = 0; ks < 32; ks++) {
        if (ks < 31) { CP_WAIT1; } else { CP_WAIT0; }
        __syncthreads();
        if (ks + 2 < 32) {
            load_stage(ks + 2, nbuf);
            if (++nbuf == 3) nbuf = 0;
        }

        #pragma unroll
        for (int kk = 0; kk < 2; kk++) {            // two k16 steps per BK=32
            uint32_t af[4][4];
            #pragma unroll
            for (int mt = 0; mt < 4; mt++) {
                uint32_t a = sA + (uint32_t)(buf * GSTAGE_B +
                              (wm + mt * 16 + (lane & 15)) * (GPH * 2) +
                              (kk * 16 + ((lane >> 4) << 3)) * 2);
                ldsm4(a, af[mt][0], af[mt][1], af[mt][2], af[mt][3]);
            }
            #pragma unroll
            for (int ntp = 0; ntp < 2; ntp++) {
                uint32_t b0, b1, b2, b3;
                uint32_t a = sB + (uint32_t)(buf * GSTAGE_B +
                              (wn + ntp * 16 + (lane & 7) + ((lane >> 4) << 3)) * (GPH * 2) +
                              (kk * 16 + (((lane >> 3) & 1) << 3)) * 2);
                ldsm4(a, b0, b1, b2, b3);
                #pragma unroll
                for (int mt = 0; mt < 4; mt++) {
                    mma_f16(acc[mt][2*ntp][0],   acc[mt][2*ntp][1],
                            acc[mt][2*ntp][2],   acc[mt][2*ntp][3],
                            af[mt][0], af[mt][1], af[mt][2], af[mt][3], b0, b1);
                    mma_f16(acc[mt][2*ntp+1][0], acc[mt][2*ntp+1][1],
                            acc[mt][2*ntp+1][2], acc[mt][2*ntp+1][3],
                            af[mt][0], af[mt][1], af[mt][2], af[mt][3], b2, b3);
                }
            }
        }
        __syncthreads();
        if (++buf == 3) buf = 0;
    }

    // Epilogue
    #pragma unroll
    for (int mt = 0; mt < 4; mt++) {
        #pragma unroll
        for (int nt = 0; nt < 4; nt++) {
            int r = bm + wm + mt * 16 + (lane >> 2);
            int c = bnc + wn + nt * 8 + ((lane & 3) << 1);
            float bv0 = bias[c], bv1 = bias[c + 1];
            float v0 = acc[mt][nt][0] + bv0, v1 = acc[mt][nt][1] + bv1;
            float v2 = acc[mt][nt][2] + bv0, v3 = acc[mt][nt][3] + bv1;
            if (mode == 3) {
                *(float2*)(dst_ext + (size_t)r * CC + c)       = make_float2(v0, v1);
                *(float2*)(dst_ext + (size_t)(r + 8) * CC + c) = make_float2(v2, v3);
            } else {
                int b = r >> 11, tt = r & 2047;
                int hn = c >> 6, d = c & 63;
                size_t bnix = (size_t)(b * NH + hn);
                if (mode == 2) {
                    g_v[(bnix * DD + d)     * TT + tt]     = __float2half_rn(v0);
                    g_v[(bnix * DD + d + 1) * TT + tt]     = __float2half_rn(v1);
                    g_v[(bnix * DD + d)     * TT + tt + 8] = __float2half_rn(v2);
                    g_v[(bnix * DD + d + 1) * TT + tt + 8] = __float2half_rn(v3);
                } else {
                    __half* dst = (mode == 0) ? g_q : g_k;
                    *(__half2*)(dst + (bnix * TT + tt) * DD + d) =
                        __floats2half2_rn(v0, v1);
                    *(__half2*)(dst + (bnix * TT + tt + 8) * DD + d) =
                        __floats2half2_rn(v2, v3);
                }
            }
        }
    }
}

// Fused QKV projection: grid (64, 8, 3); blockIdx.z = mode/W select
__global__ __launch_bounds__(256) void gemm_qkv(const float* __restrict__ bq,
                                                const float* __restrict__ bk,
                                                const float* __restrict__ bv)
{
    extern __shared__ char smem[];
    const int z = blockIdx.z;
    const float* bias = (z == 0) ? bq : (z == 1) ? bk : bv;
    gemm_body(g_x, g_wt + (size_t)z * CC * CC, bias, nullptr, z, smem,
              blockIdx.x * 128, blockIdx.y * 128);
}

// Output projection
__global__ __launch_bounds__(256) void gemm_out(const float* __restrict__ bo,
                                                float* __restrict__ out)
{
    extern __shared__ char smem[];
    gemm_body(g_attn, g_wt + 3 * (size_t)CC * CC, bo, out, 3, smem,
              blockIdx.x * 128, blockIdx.y * 128);
}

// ---------------------------------------------------------------------------
// Single-pass causal attention (f16 mma).
// P is kept in registers (A-frag == C-frag layout) for the PV mma AND staged
// to smem purely as transport for the COALESCED uint4 g_pw store, which is
// issued after the PV mma (off the critical path).
// Grid (32 qtiles reversed, 64 bn), block 128 (4 warps x 16 q-rows).
// smem pitch 72 halfs (144B) -> conflict-free b16 ldmatrix.
// ---------------------------------------------------------------------------
#define APH 72
#define ATTN_SMEM (3 * 64 * APH * 2)

__global__ __launch_bounds__(128) void attn_f16(void)
{
    extern __shared__ char smc[];
    __half* Qs = (__half*)smc;            // [64][APH]  (reused as P stage)
    __half* Ks = Qs + 64 * APH;           // [64][APH]  [tok][d]
    __half* Vs = Ks + 64 * APH;           // [64][APH]  [d][tok]

    const int t = threadIdx.x, lane = t & 31, wid = t >> 5;
    const int qb = gridDim.x - 1 - blockIdx.x;   // longest blocks first
    const int bn = blockIdx.y;
    const int q0 = qb * 64;

    const __half* __restrict__ Qg = g_q + (size_t)bn * TT * DD;
    const __half* __restrict__ Kg = g_k + (size_t)bn * TT * DD;
    const __half* __restrict__ Vg = g_v + (size_t)bn * DD * TT;

    // Load Q tile [64][64] halfs
    #pragma unroll
    for (int i = 0; i < 4; i++) {
        int lin = t + 128 * i;            // 0..511
        int row = lin >> 3;               // 0..63
        int c8  = (lin & 7) << 3;         // 0..56
        *(uint4*)(Qs + row * APH + c8) = *(const uint4*)(Qg + (size_t)(q0 + row) * DD + c8);
    }
    __syncthreads();

    const uint32_t sQ = smem_u32(Qs), sK = smem_u32(Ks), sV = smem_u32(Vs);

    // Q fragments (persistent): 4 k16-steps x 4 regs
    uint32_t qf[4][4];
    #pragma unroll
    for (int ds = 0; ds < 4; ds++) {
        uint32_t a = sQ + (uint32_t)(((wid * 16 + (lane & 15)) * APH +
                          ds * 16 + ((lane >> 4) << 3)) << 1);
        ldsm4(a, qf[ds][0], qf[ds][1], qf[ds][2], qf[ds][3]);
    }

    float o[8][4] = {};
    float l0 = 0.f, l1 = 0.f;
    const int rl = lane >> 2;
    const int cl = (lane & 3) << 1;
    const int rowg0 = q0 + wid * 16 + rl;
    const int rowg1 = rowg0 + 8;
    __half* pwbase = g_pw + ((size_t)bn * TT + q0) * TT;   // tile rows base

    for (int kt = 0; kt <= qb; kt++) {
        __syncthreads();
        #pragma unroll
        for (int i = 0; i < 4; i++) {
            int lin = t + 128 * i;
            int row = lin >> 3;
            int c8  = (lin & 7) << 3;
            *(uint4*)(Ks + row * APH + c8) =
                *(const uint4*)(Kg + (size_t)(kt * 64 + row) * DD + c8);
            *(uint4*)(Vs + row * APH + c8) =
                *(const uint4*)(Vg + (size_t)row * TT + kt * 64 + c8);
        }
        __syncthreads();

        // ---- scores + exp; P kept in registers AND staged to smem ----
        uint32_t ph[8][2];                 // [nt] {h01(rows rl), h23(rows rl+8)}
        #pragma unroll
        for (int ntp = 0; ntp < 4; ntp++) {
            float sa[2][4] = {};
            #pragma unroll
            for (int ds = 0; ds < 4; ds++) {
                uint32_t b0, b1, b2, b3;
                uint32_t a = sK + (uint32_t)(((ntp * 16 + (lane & 7) + ((lane >> 4) << 3)) * APH +
                                  ds * 16 + (((lane >> 3) & 1) << 3)) << 1);
                ldsm4(a, b0, b1, b2, b3);
                mma_f16(sa[0][0], sa[0][1], sa[0][2], sa[0][3],
                        qf[ds][0], qf[ds][1], qf[ds][2], qf[ds][3], b0, b1);
                mma_f16(sa[1][0], sa[1][1], sa[1][2], sa[1][3],
                        qf[ds][0], qf[ds][1], qf[ds][2], qf[ds][3], b2, b3);
            }
            #pragma unroll
            for (int h = 0; h < 2; h++) {
                int nt = 2 * ntp + h;
                int colg = kt * 64 + nt * 8 + cl;
                float p0 = __expf(sa[h][0] * 0.125f);
                float p1 = __expf(sa[h][1] * 0.125f);
                float p2 = __expf(sa[h][2] * 0.125f);
                float p3 = __expf(sa[h][3] * 0.125f);
                if (kt == qb) {
                    if (colg     > rowg0) p0 = 0.f;
                    if (colg + 1 > rowg0) p1 = 0.f;
                    if (colg     > rowg1) p2 = 0.f;
                    if (colg + 1 > rowg1) p3 = 0.f;
                }
                __half2 h01 = __floats2half2_rn(p0, p1);
                __half2 h23 = __floats2half2_rn(p2, p3);
                float2 f01 = __half22float2(h01);
                float2 f23 = __half22float2(h23);
                l0 += f01.x + f01.y;
                l1 += f23.x + f23.y;
                int lr = wid * 16 + rl, lc = nt * 8 + cl;
                *(__half2*)(Qs + lr * APH + lc)       = h01;
                *(__half2*)(Qs + (lr + 8) * APH + lc) = h23;
                ph[nt][0] = *(uint32_t*)&h01;
                ph[nt][1] = *(uint32_t*)&h23;
            }
        }

        // ---- O += P @ V  (P A-frags straight from registers) ----
        #pragma unroll
        for (int ntp = 0; ntp < 4; ntp++) {
            #pragma unroll
            for (int kp = 0; kp < 4; kp++) {
                uint32_t b0, b1, b2, b3;
                uint32_t a = sV + (uint32_t)(((ntp * 16 + (lane & 7) + ((lane >> 4) << 3)) * APH +
                                  kp * 16 + (((lane >> 3) & 1) << 3)) << 1);
                ldsm4(a, b0, b1, b2, b3);
                mma_f16(o[2*ntp][0], o[2*ntp][1], o[2*ntp][2], o[2*ntp][3],
                        ph[2*kp][0], ph[2*kp][1], ph[2*kp+1][0], ph[2*kp+1][1], b0, b1);
                mma_f16(o[2*ntp+1][0], o[2*ntp+1][1], o[2*ntp+1][2], o[2*ntp+1][3],
                        ph[2*kp][0], ph[2*kp][1], ph[2*kp+1][0], ph[2*kp+1][1], b2, b3);
            }
        }

        // ---- coalesced store of this warp's 16 p-rows (off critical path) ----
        __syncwarp();
        #pragma unroll
        for (int it = 0; it < 4; it++) {
            int idx = lane + 32 * it;        // 0..127
            int r16 = idx >> 3;              // 0..15
            int c8  = (idx & 7) << 3;        // 0..56
            int lr  = wid * 16 + r16;
            *(uint4*)(pwbase + (size_t)lr * TT + kt * 64 + c8) =
                *(const uint4*)(Qs + lr * APH + c8);
        }
    }

    // row sums -> 1/l
    l0 += __shfl_xor_sync(0xffffffffu, l0, 1);
    l0 += __shfl_xor_sync(0xffffffffu, l0, 2);
    l1 += __shfl_xor_sync(0xffffffffu, l1, 1);
    l1 += __shfl_xor_sync(0xffffffffu, l1, 2);
    float li0 = 1.f / l0, li1 = 1.f / l1;

    // store O (normalized, f16) in [b][t][hn*64+d]
    int b = bn >> 4, hn = bn & 15;
    __half* Og0 = g_attn + ((size_t)b * TT + rowg0) * CC + hn * DD;
    __half* Og1 = g_attn + ((size_t)b * TT + rowg1) * CC + hn * DD;
    #pragma unroll
    for (int nt = 0; nt < 8; nt++) {
        *(__half2*)(Og0 + nt * 8 + cl) = __floats2half2_rn(o[nt][0] * li0, o[nt][1] * li0);
        *(__half2*)(Og1 + nt * 8 + cl) = __floats2half2_rn(o[nt][2] * li1, o[nt][3] * li1);
    }
    if ((lane & 3) == 0) {
        g_linv[(size_t)bn * TT + rowg0] = li0;
        g_linv[(size_t)bn * TT + rowg1] = li1;
    }
}

// ---------------------------------------------------------------------------
// Produce final fp32 weights: normalize f16 staging for cols<=q, zeros above.
// One block (256 threads) per row; writes the FULL 2048-col row once.
// ---------------------------------------------------------------------------
__global__ __launch_bounds__(256) void scale_w_kernel(float* __restrict__ w)
{
    int R = blockIdx.x;                  // 0 .. 64*2048-1
    int q = R & 2047;
    float li = g_linv[R];
    const __half* src = g_pw + (size_t)R * TT;
    float* row = w + (size_t)R * TT;
    #pragma unroll
    for (int i = 0; i < 2; i++) {
        int col = (threadIdx.x + (i << 8)) << 2;
        float4 v;
        if (col <= q) {
            __half2 a = *(const __half2*)(src + col);
            __half2 b = *(const __half2*)(src + col + 2);
            float2 fa = __half22float2(a);
            float2 fb = __half22float2(b);
            v.x = fa.x * li;
            v.y = (col + 1 <= q) ? fa.y * li : 0.f;
            v.z = (col + 2 <= q) ? fb.x * li : 0.f;
            v.w = (col + 3 <= q) ? fb.y * li : 0.f;
        } else {
            v = make_float4(0.f, 0.f, 0.f, 0.f);
        }
        *(float4*)(row + col) = v;
    }
}

// ---------------------------------------------------------------------------
extern "C" void kernel_launch(void* const* d_in, const int* in_sizes, int n_in,
                              void* d_out, int out_size)
{
    const float* x  = (const float*)d_in[0];
    const float* Wq = (const float*)d_in[1];
    const float* bq = (const float*)d_in[2];
    const float* Wk = (const float*)d_in[3];
    const float* bk = (const float*)d_in[4];
    const float* Wv = (const float*)d_in[5];
    const float* bv = (const float*)d_in[6];
    const float* Wo = (const float*)d_in[7];
    const float* bo = (const float*)d_in[8];
    float* out = (float*)d_out;
    float* w_out = out + OUT_ELEMS;

    cudaFuncSetAttribute(gemm_qkv, cudaFuncAttributeMaxDynamicSharedMemorySize, GEMM_SMEM);
    cudaFuncSetAttribute(gemm_out, cudaFuncAttributeMaxDynamicSharedMemorySize, GEMM_SMEM);
    cudaFuncSetAttribute(attn_f16, cudaFuncAttributeMaxDynamicSharedMemorySize, ATTN_SMEM);

    // Pre-pass
    round_x_kernel<<<(MROWS * CC) / (256 * 8), 256>>>(x);
    dim3 tg(32, 32, 4);
    transpose_w_all<<<tg, 256>>>(Wq, Wk, Wv, Wo);

    dim3 gq(MROWS / 128, CC / 128, 3);
    gemm_qkv<<<gq, 256, GEMM_SMEM>>>(bq, bk, bv);

    dim3 ag(TT / 64, BB * NH);
    attn_f16<<<ag, 128, ATTN_SMEM>>>();

    dim3 gg(MROWS / 128, CC / 128);
    gemm_out<<<gg, 256, GEMM_SMEM>>>(bo, out);

    scale_w_kernel<<<BB * NH * TT, 256>>>(w_out);
}